// round 8
// baseline (speedup 1.0000x reference)
#include <cuda_runtime.h>
#include <math.h>

// ---------------- problem constants ----------------
#define BB    1024
#define NN_   80
#define CC    51     // OUTP
#define DM_   26
#define NEGV  -1e30f

#define DIST_OFF 16384
#define A_OFF    (16384 + 1024*6400)

typedef unsigned long long u64;

// ---------------- f32x2 packed helpers ----------------
__device__ __forceinline__ u64 pk2(float lo, float hi) {
    u64 r; asm("mov.b64 %0,{%1,%2};" : "=l"(r) : "f"(lo), "f"(hi)); return r;
}
__device__ __forceinline__ u64 dup2(float v) { return pk2(v, v); }
__device__ __forceinline__ void up2(u64 v, float& a, float& b) {
    asm("mov.b64 {%0,%1},%2;" : "=f"(a), "=f"(b) : "l"(v));
}
__device__ __forceinline__ u64 fma2(u64 a, u64 b, u64 c) {
    u64 d; asm("fma.rn.f32x2 %0,%1,%2,%3;" : "=l"(d) : "l"(a), "l"(b), "l"(c)); return d;
}
__device__ __forceinline__ float f4c(const float4& v, int kk) {
    return (kk == 0) ? v.x : (kk == 1) ? v.y : (kk == 2) ? v.z : v.w;
}

// ---------------- device scratch / prepped constants ----------------
__device__ float g_x[BB * NN_ * CC];
__device__ float g_An11[64 * 64];
__device__ float g_An22[16 * 16];
__device__ unsigned int g_AtmBits[32];
__device__ float g_Wg1aT[52 * 64];   // [k][o], row 51 zero
__device__ float g_Wg2aT[51 * 64];   // [k][o]
__device__ float g_Wg1bT[64 * 64];   // [h][o2], o2>=50 zero
__device__ float g_thetaB[52 * 64];  // [c][r], r>=50 zero, rows 50,51 zero
__device__ float g_coef;

// =====================================================================
// setup work: executed by one extra block of k_mlp (512 threads)
// =====================================================================
__device__ void do_setup(float* sh,
                         const float* __restrict__ M, const float* __restrict__ Wk,
                         const float* __restrict__ smoothing,
                         const float* __restrict__ Wg1a, const float* __restrict__ Wg1b,
                         const float* __restrict__ Wg2a,
                         float* __restrict__ outA)
{
    float* sM = sh;                 // 80*26
    float* sA = sM + NN_ * DM_;     // 80*80
    float* d1 = sA + NN_ * NN_;     // 64
    float* d2 = d1 + 64;            // 16
    const int tid = threadIdx.x;
    const int lane = tid & 31, warp = tid >> 5;   // 16 warps

    for (int e = tid; e < NN_ * DM_; e += 512) sM[e] = M[e];
    for (int e = tid; e < NN_ * NN_; e += 512) sA[e] = 0.f;
    __syncthreads();

    for (int p = warp; p < NN_; p += 16) {
        float vals[3];
        float mx = NEGV;
        int cnt = 0;
        for (int q = lane; q < p; q += 32) {
            float s = 0.f;
            #pragma unroll
            for (int k = 0; k < DM_; k++) s = fmaf(sM[p * DM_ + k], sM[q * DM_ + k], s);
            s = fmaxf(s, 0.f);
            vals[cnt++] = s;
            mx = fmaxf(mx, s);
        }
        #pragma unroll
        for (int off = 16; off; off >>= 1) mx = fmaxf(mx, __shfl_xor_sync(0xffffffffu, mx, off));
        float sum = 0.f;
        for (int c = 0; c < cnt; c++) { vals[c] = expf(vals[c] - mx); sum += vals[c]; }
        #pragma unroll
        for (int off = 16; off; off >>= 1) sum += __shfl_xor_sync(0xffffffffu, sum, off);
        float inv = (p > 0) ? 1.f / sum : 0.f;
        cnt = 0;
        for (int q = lane; q < p; q += 32) sA[p * NN_ + q] = vals[cnt++] * inv;
    }
    __syncthreads();

    for (int e = tid; e < NN_ * NN_; e += 512) outA[e] = sA[e];

    if (tid < 64) {
        int c = 0;
        for (int q = 0; q < 64; q++) c += (sA[tid * NN_ + q] > 1e-15f) ? 1 : 0;
        d1[tid] = rsqrtf(1.f + (float)c);
    } else if (tid < 80) {
        int p = tid;
        int c = 0;
        for (int q = 64; q < 80; q++) c += (sA[p * NN_ + q] > 1e-15f) ? 1 : 0;
        d2[tid - 64] = rsqrtf(1.f + (float)c);
    }
    __syncthreads();

    for (int e = tid; e < 64 * 64; e += 512) {
        int p = e >> 6, q = e & 63;
        g_An11[e] = d1[p] * sA[p * NN_ + q] * d1[q];
    }
    if (tid < 256) {
        int p = tid >> 4, q = tid & 15;
        g_An22[tid] = d2[p] * sA[(64 + p) * NN_ + 64 + q] * d2[q];
    }

    if (tid < 16) {
        int p = 64 + tid;
        float mx = NEGV;
        for (int i = 0; i < 64; i++) {
            float a = sA[p * NN_ + i];
            mx = fmaxf(mx, (a != 0.f) ? a : NEGV);
        }
        float sum = 0.f;
        for (int i = 0; i < 64; i++) {
            float a = sA[p * NN_ + i];
            sum += expf(((a != 0.f) ? a : NEGV) - mx);
        }
        float inv = 1.f / sum;
        unsigned int b0 = 0u, b1 = 0u;
        for (int i = 0; i < 64; i++) {
            float a = sA[p * NN_ + i];
            float v = expf(((a != 0.f) ? a : NEGV) - mx) * inv;
            if (v >= 0.004f) {
                if (i < 32) b0 |= (1u << i);
                else        b1 |= (1u << (i - 32));
            }
        }
        g_AtmBits[tid * 2]     = b0;
        g_AtmBits[tid * 2 + 1] = b1;
    }

    // theta (padded): rows >=50 zero, cols r>=50 zero
    for (int e = tid; e < 52 * 64; e += 512) {
        int c = e >> 6, r = e & 63;
        float s = 0.f;
        if (c < 50 && r < 50) {
            #pragma unroll 8
            for (int k = 0; k < 64; k++) s = fmaf(Wk[c * 64 + k], Wk[r * 64 + k], s);
        }
        g_thetaB[e] = s;
    }

    // transposed weights
    for (int e = tid; e < 52 * 64; e += 512) {
        int k = e >> 6, o = e & 63;
        g_Wg1aT[e] = (k < 51) ? Wg1a[o * 51 + k] : 0.f;
    }
    for (int e = tid; e < 51 * 64; e += 512) {
        int k = e >> 6, o = e & 63;
        g_Wg2aT[e] = Wg2a[o * 51 + k];
    }
    for (int e = tid; e < 64 * 64; e += 512) {
        int h = e >> 6, o = e & 63;
        g_Wg1bT[e] = (o < 50) ? Wg1b[o * 64 + h] : 0.f;
    }

    if (tid == 0) {
        float sg = 1.f / (1.f + expf(-smoothing[0]));
        g_coef = -0.5f / (sg * 0.01f);
    }
}

// =====================================================================
// Kernel 1: gather + 3-layer MLP. 512 threads, 4x4 tiles, 2 CTAs/SM.
// =====================================================================
#define PT  68   // token buffer pitch (mult of 4)
#define PW1 52   // staged w1 pitch (mult of 4)

__global__ void __launch_bounds__(512, 2) k_mlp(
    const float* __restrict__ data,
    const float* __restrict__ emb0, const float* __restrict__ emb1, const float* __restrict__ emb2,
    const float* __restrict__ w1, const float* __restrict__ b1,
    const float* __restrict__ w2, const float* __restrict__ b2,
    const float* __restrict__ w3, const float* __restrict__ b3,
    const float* __restrict__ M, const float* __restrict__ Wk,
    const float* __restrict__ smoothing,
    const float* __restrict__ Wg1a, const float* __restrict__ Wg1b,
    const float* __restrict__ Wg2a,
    float* __restrict__ outA)
{
    extern __shared__ float sh[];

    if (blockIdx.x == 1280) {
        do_setup(sh, M, Wk, smoothing, Wg1a, Wg1b, Wg2a, outA);
        return;
    }

    float* T     = sh;               // 128 * PT (feature-major: [feat][token])
    float* w1s   = T + 128 * PT;     // 128 * PW1
    float* sLast = w1s + 128 * PW1;  // 64

    const int tid = threadIdx.x;
    const int cx = tid & 15, ry = tid >> 4;   // cx: 4 tokens, ry: 0..31
    const int base = blockIdx.x * 64;

    if (tid < 64) sLast[tid] = data[(size_t)(base + tid) * 6 + 5];

    // stage w1 (128 x 51 -> pitch 52, col 51 zero)
    for (int e = tid; e < 128 * PW1; e += 512) {
        int o = e / PW1, k = e % PW1;
        w1s[e] = (k < 51) ? w1[o * 51 + k] : 0.f;
    }
    // gather X^T (52 x 64): T[c][t], row 51 zero
    for (int e = tid; e < 52 * 64; e += 512) {
        int c = e >> 6, t = e & 63;
        const float* dr = data + (size_t)(base + t) * 6;
        float v;
        if (c < 32)      { int i0 = (int)dr[0]; v = emb0[i0 * 32 + c]; }
        else if (c < 40) { int i1 = (int)dr[1]; v = emb1[i1 * 8 + (c - 32)]; }
        else if (c < 48) { int i2 = (int)dr[2]; v = emb2[i2 * 8 + (c - 40)]; }
        else if (c < 51) { v = dr[3 + (c - 48)]; }
        else             { v = 0.f; }
        T[c * PT + t] = v;
    }
    __syncthreads();

    // ---- GEMM1: h1[o][t] = relu(w1s @ T + b1), K=52, rows o = ry + 32*i ----
    {
        u64 acc[4][2];
        #pragma unroll
        for (int i = 0; i < 4; i++) { acc[i][0] = 0ull; acc[i][1] = 0ull; }
        for (int k0 = 0; k0 < 52; k0 += 4) {
            float4 ap[4];
            #pragma unroll
            for (int i = 0; i < 4; i++)
                ap[i] = *reinterpret_cast<const float4*>(&w1s[(ry + 32 * i) * PW1 + k0]);
            #pragma unroll
            for (int kk = 0; kk < 4; kk++) {
                ulonglong2 bv = *reinterpret_cast<const ulonglong2*>(&T[(k0 + kk) * PT + 4 * cx]);
                #pragma unroll
                for (int i = 0; i < 4; i++) {
                    u64 ad = dup2(f4c(ap[i], kk));
                    acc[i][0] = fma2(ad, bv.x, acc[i][0]);
                    acc[i][1] = fma2(ad, bv.y, acc[i][1]);
                }
            }
        }
        __syncthreads();
        #pragma unroll
        for (int i = 0; i < 4; i++) {
            int o = ry + 32 * i;
            float bo = __ldg(&b1[o]);
            float4 v;
            up2(acc[i][0], v.x, v.y);
            up2(acc[i][1], v.z, v.w);
            v.x = fmaxf(v.x + bo, 0.f); v.y = fmaxf(v.y + bo, 0.f);
            v.z = fmaxf(v.z + bo, 0.f); v.w = fmaxf(v.w + bo, 0.f);
            *reinterpret_cast<float4*>(&T[o * PT + 4 * cx]) = v;
        }
        __syncthreads();
    }

    // ---- GEMM2: h2 = relu(w2 @ T + b2), K=128 ----
    {
        u64 acc[4][2];
        #pragma unroll
        for (int i = 0; i < 4; i++) { acc[i][0] = 0ull; acc[i][1] = 0ull; }
        #pragma unroll 2
        for (int k0 = 0; k0 < 128; k0 += 4) {
            float4 ap[4];
            #pragma unroll
            for (int i = 0; i < 4; i++)
                ap[i] = *reinterpret_cast<const float4*>(&w2[(ry + 32 * i) * 128 + k0]);
            #pragma unroll
            for (int kk = 0; kk < 4; kk++) {
                ulonglong2 bv = *reinterpret_cast<const ulonglong2*>(&T[(k0 + kk) * PT + 4 * cx]);
                #pragma unroll
                for (int i = 0; i < 4; i++) {
                    u64 ad = dup2(f4c(ap[i], kk));
                    acc[i][0] = fma2(ad, bv.x, acc[i][0]);
                    acc[i][1] = fma2(ad, bv.y, acc[i][1]);
                }
            }
        }
        __syncthreads();
        #pragma unroll
        for (int i = 0; i < 4; i++) {
            int o = ry + 32 * i;
            float bo = __ldg(&b2[o]);
            float4 v;
            up2(acc[i][0], v.x, v.y);
            up2(acc[i][1], v.z, v.w);
            v.x = fmaxf(v.x + bo, 0.f); v.y = fmaxf(v.y + bo, 0.f);
            v.z = fmaxf(v.z + bo, 0.f); v.w = fmaxf(v.w + bo, 0.f);
            *reinterpret_cast<float4*>(&T[o * PT + 4 * cx]) = v;
        }
        __syncthreads();
    }

    // ---- GEMM3: h3 = w3 @ T + b3 (o<50) -> g_x, K=128, rows o = ry + 32*i, i<2 ----
    {
        u64 acc[2][2];
        #pragma unroll
        for (int i = 0; i < 2; i++) { acc[i][0] = 0ull; acc[i][1] = 0ull; }
        #pragma unroll 2
        for (int k0 = 0; k0 < 128; k0 += 4) {
            float4 ap[2];
            #pragma unroll
            for (int i = 0; i < 2; i++) {
                int o = ry + 32 * i;
                ap[i] = (o < 50) ? *reinterpret_cast<const float4*>(&w3[o * 128 + k0])
                                 : make_float4(0.f, 0.f, 0.f, 0.f);
            }
            #pragma unroll
            for (int kk = 0; kk < 4; kk++) {
                ulonglong2 bv = *reinterpret_cast<const ulonglong2*>(&T[(k0 + kk) * PT + 4 * cx]);
                #pragma unroll
                for (int i = 0; i < 2; i++) {
                    u64 ad = dup2(f4c(ap[i], kk));
                    acc[i][0] = fma2(ad, bv.x, acc[i][0]);
                    acc[i][1] = fma2(ad, bv.y, acc[i][1]);
                }
            }
        }
        #pragma unroll
        for (int i = 0; i < 2; i++) {
            int o = ry + 32 * i;
            if (o < 50) {
                float bo = __ldg(&b3[o]);
                float v0, v1, v2, v3;
                up2(acc[i][0], v0, v1);
                up2(acc[i][1], v2, v3);
                int t = base + 4 * cx;
                g_x[(size_t)(t + 0) * CC + o] = v0 + bo;
                g_x[(size_t)(t + 1) * CC + o] = v1 + bo;
                g_x[(size_t)(t + 2) * CC + o] = v2 + bo;
                g_x[(size_t)(t + 3) * CC + o] = v3 + bo;
            }
        }
        if (tid < 64) g_x[(size_t)(base + tid) * CC + 50] = sLast[tid];
    }
}

// =====================================================================
// Kernel 2: per-graph pipeline. 512 threads, 2x4 gemm tiles, 2 CTAs/SM.
// =====================================================================
#define PXM 52   // xs pitch (mult of 4)
#define PZB 68   // big buffer pitch (mult of 4)
#define PQ  66   // small 16-row buffer pitch (even)

// C(64x64) = A(64xK smem, pitch pa) @ B(Kx64 global, ld 64). K mult of 4.
// Rows = ry + 32*i (ry 0..31, i 0..1). C may alias A.
__device__ __forceinline__ void gemm_AS_BG(const float* As, int pa,
                                           const float* __restrict__ Bg, int K,
                                           float* Cs, bool do_relu, int cx, int ry)
{
    u64 acc[2][2];
    #pragma unroll
    for (int i = 0; i < 2; i++) { acc[i][0] = 0ull; acc[i][1] = 0ull; }
    for (int k0 = 0; k0 < K; k0 += 4) {
        float4 ap[2];
        #pragma unroll
        for (int i = 0; i < 2; i++)
            ap[i] = *reinterpret_cast<const float4*>(As + (ry + 32 * i) * pa + k0);
        #pragma unroll
        for (int kk = 0; kk < 4; kk++) {
            ulonglong2 bv = *reinterpret_cast<const ulonglong2*>(Bg + (k0 + kk) * 64 + 4 * cx);
            #pragma unroll
            for (int i = 0; i < 2; i++) {
                u64 ad = dup2(f4c(ap[i], kk));
                acc[i][0] = fma2(ad, bv.x, acc[i][0]);
                acc[i][1] = fma2(ad, bv.y, acc[i][1]);
            }
        }
    }
    __syncthreads();
    #pragma unroll
    for (int i = 0; i < 2; i++) {
        float4 v;
        up2(acc[i][0], v.x, v.y);
        up2(acc[i][1], v.z, v.w);
        if (do_relu) {
            v.x = fmaxf(v.x, 0.f); v.y = fmaxf(v.y, 0.f);
            v.z = fmaxf(v.z, 0.f); v.w = fmaxf(v.w, 0.f);
        }
        *reinterpret_cast<float4*>(&Cs[(ry + 32 * i) * PZB + 4 * cx]) = v;
    }
    __syncthreads();
}

// C(64x64) = A(64x64 global, ld 64) @ B(64x64 smem, pitch PZB). C may alias B.
__device__ __forceinline__ void gemm_AG_BS(const float* __restrict__ Ag,
                                           const float* Bs,
                                           float* Cs, bool do_relu, int cx, int ry)
{
    u64 acc[2][2];
    #pragma unroll
    for (int i = 0; i < 2; i++) { acc[i][0] = 0ull; acc[i][1] = 0ull; }
    for (int k0 = 0; k0 < 64; k0 += 4) {
        float4 ap[2];
        #pragma unroll
        for (int i = 0; i < 2; i++)
            ap[i] = *reinterpret_cast<const float4*>(Ag + (ry + 32 * i) * 64 + k0);
        #pragma unroll
        for (int kk = 0; kk < 4; kk++) {
            ulonglong2 bv = *reinterpret_cast<const ulonglong2*>(&Bs[(k0 + kk) * PZB + 4 * cx]);
            #pragma unroll
            for (int i = 0; i < 2; i++) {
                u64 ad = dup2(f4c(ap[i], kk));
                acc[i][0] = fma2(ad, bv.x, acc[i][0]);
                acc[i][1] = fma2(ad, bv.y, acc[i][1]);
            }
        }
    }
    __syncthreads();
    #pragma unroll
    for (int i = 0; i < 2; i++) {
        float4 v;
        up2(acc[i][0], v.x, v.y);
        up2(acc[i][1], v.z, v.w);
        if (do_relu) {
            v.x = fmaxf(v.x, 0.f); v.y = fmaxf(v.y, 0.f);
            v.z = fmaxf(v.z, 0.f); v.w = fmaxf(v.w, 0.f);
        }
        *reinterpret_cast<float4*>(&Cs[(ry + 32 * i) * PZB + 4 * cx]) = v;
    }
    __syncthreads();
}

__global__ void __launch_bounds__(512, 2) k_main(
    const float* __restrict__ Wg2b,
    float* __restrict__ dout)
{
    extern __shared__ float sh[];
    float* xs  = sh;                 // 80*PXM
    float* B1  = xs + 80 * PXM;      // 64*PZB
    float* B2  = B1 + 64 * PZB;      // 64*PZB
    float* z3  = B2 + 64 * PZB;      // 16*PQ
    float* t2b = z3 + 16 * PQ;       // 16*PQ
    float* Ls  = t2b + 16 * PQ;      // 16*PQ
    float* yhv = Ls + 16 * PQ;       // 16
    float* z4v = yhv + 16;           // 16
    float* sqv = z4v + 16;           // 80

    const int tid = threadIdx.x;
    const int cx = tid & 15, ry = tid >> 4;          // gemm tiling (ry 0..31)
    const int tx = tid & 15, ty16 = tid >> 4;        // 256-thread sections (guarded)
    const int b = blockIdx.x;
    const float* gx = g_x + (size_t)b * NN_ * CC;

    // -------- load per-graph features (pitch 52, col 51 zero) --------
    for (int e = tid; e < 80 * PXM; e += 512) {
        int r = e / PXM, c = e % PXM;
        xs[e] = (c < 51) ? gx[r * 51 + c] : 0.f;
    }
    __syncthreads();

    // -------- gcnn1 chain --------
    gemm_AS_BG(xs, PXM, g_Wg1aT, 52, B1, false, cx, ry);   // z1
    gemm_AG_BS(g_An11, B1, B1, true, cx, ry);              // t1 = relu(An11 @ z1)
    gemm_AS_BG(B1, PZB, g_Wg1bT, 64, B1, false, cx, ry);   // z2
    gemm_AG_BS(g_An11, B1, B2, false, cx, ry);             // x1 -> B2
    gemm_AS_BG(B2, PZB, g_thetaB, 52, B1, false, cx, ry);  // u  -> B1

    // -------- v = xf @ theta (16x64) -> z3 --------
    if (tid < 256) {
        u64 acc[2] = {0ull, 0ull};
        for (int k = 0; k < 50; k += 2) {
            float2 a = *reinterpret_cast<const float2*>(&xs[(64 + ty16) * PXM + k]);
            u64 a0 = dup2(a.x), a1 = dup2(a.y);
            acc[0] = fma2(a0, *reinterpret_cast<const u64*>(&g_thetaB[k * 64 + 2 * tx]), acc[0]);
            acc[1] = fma2(a0, *reinterpret_cast<const u64*>(&g_thetaB[k * 64 + 2 * tx + 32]), acc[1]);
            acc[0] = fma2(a1, *reinterpret_cast<const u64*>(&g_thetaB[(k + 1) * 64 + 2 * tx]), acc[0]);
            acc[1] = fma2(a1, *reinterpret_cast<const u64*>(&g_thetaB[(k + 1) * 64 + 2 * tx + 32]), acc[1]);
        }
        #pragma unroll
        for (int j = 0; j < 2; j++) {
            float v0, v1; up2(acc[j], v0, v1);
            int c = 2 * tx + 32 * j;
            z3[ty16 * PQ + c] = v0;
            z3[ty16 * PQ + c + 1] = v1;
        }
    }
    __syncthreads();

    // -------- q[j][i] = (xp_i - xf_j).(u_i - v_j) -> masked logits Ls --------
    if (tid < 256) {
        float cf = g_coef;
        float acc[4] = {0.f, 0.f, 0.f, 0.f};
        for (int k = 0; k < 50; k += 2) {
            float2 xf2 = *reinterpret_cast<const float2*>(&xs[(64 + ty16) * PXM + k]);
            float2 v2  = *reinterpret_cast<const float2*>(&z3[ty16 * PQ + k]);
            #pragma unroll
            for (int j = 0; j < 4; j++) {
                int i = tx + 16 * j;
                float2 b2v = *reinterpret_cast<const float2*>(&B2[i * PZB + k]);
                float2 b1v = *reinterpret_cast<const float2*>(&B1[i * PZB + k]);
                acc[j] = fmaf(b2v.x - xf2.x, b1v.x - v2.x, acc[j]);
                acc[j] = fmaf(b2v.y - xf2.y, b1v.y - v2.y, acc[j]);
            }
        }
        unsigned int m0 = __ldg(&g_AtmBits[ty16 * 2]);
        unsigned int m1 = __ldg(&g_AtmBits[ty16 * 2 + 1]);
        #pragma unroll
        for (int j = 0; j < 4; j++) {
            int i = tx + 16 * j;
            bool on = (i < 32) ? ((m0 >> i) & 1u) : ((m1 >> (i - 32)) & 1u);
            Ls[ty16 * PQ + i] = on ? (cf * acc[j]) : NEGV;
        }
    }
    __syncthreads();

    // -------- softmax over j --------
    if (tid < 64) {
        int i = tid;
        float m = NEGV;
        for (int j = 0; j < 16; j++) m = fmaxf(m, Ls[j * PQ + i]);
        float s = 0.f;
        for (int j = 0; j < 16; j++) {
            float e = expf(Ls[j * PQ + i] - m);
            Ls[j * PQ + i] = e;
            s += e;
        }
        float inv = 1.f / s;
        for (int j = 0; j < 16; j++) Ls[j * PQ + i] *= inv;
    }
    __syncthreads();

    // -------- yh, splice --------
    if (tid < 16) {
        float s = 0.f;
        for (int i = 0; i < 64; i++) s = fmaf(Ls[tid * PQ + i], xs[i * PXM + 50], s);
        yhv[tid] = s;
    }
    __syncthreads();
    if (tid < 16) xs[(64 + tid) * PXM + 50] = yhv[tid];
    __syncthreads();

    // -------- gcnn2: z3g = x2 @ Wg2a^T (16x64), K=51 --------
    if (tid < 256) {
        u64 acc[2] = {0ull, 0ull};
        for (int k = 0; k < 50; k += 2) {
            float2 a = *reinterpret_cast<const float2*>(&xs[(64 + ty16) * PXM + k]);
            u64 a0 = dup2(a.x), a1 = dup2(a.y);
            acc[0] = fma2(a0, *reinterpret_cast<const u64*>(&g_Wg2aT[k * 64 + 2 * tx]), acc[0]);
            acc[1] = fma2(a0, *reinterpret_cast<const u64*>(&g_Wg2aT[k * 64 + 2 * tx + 32]), acc[1]);
            acc[0] = fma2(a1, *reinterpret_cast<const u64*>(&g_Wg2aT[(k + 1) * 64 + 2 * tx]), acc[0]);
            acc[1] = fma2(a1, *reinterpret_cast<const u64*>(&g_Wg2aT[(k + 1) * 64 + 2 * tx + 32]), acc[1]);
        }
        { // k = 50
            u64 a0 = dup2(xs[(64 + ty16) * PXM + 50]);
            acc[0] = fma2(a0, *reinterpret_cast<const u64*>(&g_Wg2aT[50 * 64 + 2 * tx]), acc[0]);
            acc[1] = fma2(a0, *reinterpret_cast<const u64*>(&g_Wg2aT[50 * 64 + 2 * tx + 32]), acc[1]);
        }
        #pragma unroll
        for (int j = 0; j < 2; j++) {
            float v0, v1; up2(acc[j], v0, v1);
            int c = 2 * tx + 32 * j;
            z3[ty16 * PQ + c] = v0;
            z3[ty16 * PQ + c + 1] = v1;
        }
    }
    __syncthreads();

    // -------- t2 = relu(An22 @ z3g) --------
    if (tid < 256) {
        u64 acc[2] = {0ull, 0ull};
        for (int q = 0; q < 16; q++) {
            u64 ad = dup2(__ldg(&g_An22[ty16 * 16 + q]));
            acc[0] = fma2(ad, *reinterpret_cast<const u64*>(&z3[q * PQ + 2 * tx]), acc[0]);
            acc[1] = fma2(ad, *reinterpret_cast<const u64*>(&z3[q * PQ + 2 * tx + 32]), acc[1]);
        }
        #pragma unroll
        for (int j = 0; j < 2; j++) {
            float v0, v1; up2(acc[j], v0, v1);
            int c = 2 * tx + 32 * j;
            t2b[ty16 * PQ + c]     = fmaxf(v0, 0.f);
            t2b[ty16 * PQ + c + 1] = fmaxf(v1, 0.f);
        }
    }
    __syncthreads();

    if (tid < 16) {
        float s = 0.f;
        for (int c = 0; c < 64; c++) s = fmaf(t2b[tid * PQ + c], __ldg(&Wg2b[c]), s);
        z4v[tid] = s;
    }
    __syncthreads();
    if (tid < 16) {
        float s = 0.f;
        for (int q = 0; q < 16; q++) s = fmaf(__ldg(&g_An22[tid * 16 + q]), z4v[q], s);
        dout[b * 16 + tid] = s;
    }

    // -------- pairwise dist on xc (80x52, col 51 zero) --------
    if (tid < 80) {
        float s = 0.f;
        for (int c = 0; c < 51; c++) {
            float v = xs[tid * PXM + c];
            s = fmaf(v, v, s);
        }
        sqv[tid] = s;
    }
    __syncthreads();
    if (tid < 400) {
        const int dx = tid % 20, dy = tid / 20;   // 20x20 grid of 4x4 tiles
        float acc[4][4];
        #pragma unroll
        for (int i = 0; i < 4; i++)
            #pragma unroll
            for (int j = 0; j < 4; j++) acc[i][j] = 0.f;
        for (int k0 = 0; k0 < 52; k0 += 4) {
            float4 a4[4], b4[4];
            #pragma unroll
            for (int i = 0; i < 4; i++)
                a4[i] = *reinterpret_cast<const float4*>(&xs[(dy * 4 + i) * PXM + k0]);
            #pragma unroll
            for (int j = 0; j < 4; j++)
                b4[j] = *reinterpret_cast<const float4*>(&xs[(dx * 4 + j) * PXM + k0]);
            #pragma unroll
            for (int i = 0; i < 4; i++)
                #pragma unroll
                for (int j = 0; j < 4; j++) {
                    acc[i][j] = fmaf(a4[i].x, b4[j].x, acc[i][j]);
                    acc[i][j] = fmaf(a4[i].y, b4[j].y, acc[i][j]);
                    acc[i][j] = fmaf(a4[i].z, b4[j].z, acc[i][j]);
                    acc[i][j] = fmaf(a4[i].w, b4[j].w, acc[i][j]);
                }
        }
        float* dd = dout + DIST_OFF + (size_t)b * 6400;
        #pragma unroll
        for (int i = 0; i < 4; i++)
            #pragma unroll
            for (int j = 0; j < 4; j++) {
                int n = dy * 4 + i, m = dx * 4 + j;
                float d2 = sqv[n] + sqv[m] - 2.f * acc[i][j];
                dd[n * 80 + m] = (d2 > 0.f) ? sqrtf(d2) : 0.f;
            }
    }
}

// =====================================================================
// launcher
// =====================================================================
extern "C" void kernel_launch(void* const* d_in, const int* in_sizes, int n_in,
                              void* d_out, int out_size)
{
    const float* data  = (const float*)d_in[0];
    const float* emb0  = (const float*)d_in[1];
    const float* emb1  = (const float*)d_in[2];
    const float* emb2  = (const float*)d_in[3];
    const float* w1    = (const float*)d_in[4];
    const float* b1    = (const float*)d_in[5];
    const float* w2    = (const float*)d_in[6];
    const float* b2    = (const float*)d_in[7];
    const float* w3    = (const float*)d_in[8];
    const float* b3    = (const float*)d_in[9];
    const float* M     = (const float*)d_in[10];
    const float* Wg1a  = (const float*)d_in[11];
    const float* Wg1b  = (const float*)d_in[12];
    const float* Wk    = (const float*)d_in[13];
    const float* smoothing = (const float*)d_in[14];
    const float* Wg2a  = (const float*)d_in[15];
    const float* Wg2b  = (const float*)d_in[16];
    float* out = (float*)d_out;

    const int SMEM_MLP  = (128 * PT + 128 * PW1 + 64) * 4;
    const int SMEM_MAIN = (80 * PXM + 2 * 64 * PZB + 3 * 16 * PQ + 16 + 16 + 80) * 4;

    cudaFuncSetAttribute(k_mlp, cudaFuncAttributeMaxDynamicSharedMemorySize, SMEM_MLP);
    cudaFuncSetAttribute(k_main, cudaFuncAttributeMaxDynamicSharedMemorySize, SMEM_MAIN);

    k_mlp<<<1281, 512, SMEM_MLP>>>(data, emb0, emb1, emb2, w1, b1, w2, b2, w3, b3,
                                   M, Wk, smoothing, Wg1a, Wg1b, Wg2a, out + A_OFF);
    k_main<<<1024, 512, SMEM_MAIN>>>(Wg2b, out);
}

// round 9
// speedup vs baseline: 1.2399x; 1.2399x over previous
#include <cuda_runtime.h>
#include <math.h>

// ---------------- problem constants ----------------
#define BB    1024
#define NN_   80
#define CC    51     // OUTP
#define DM_   26
#define NEGV  -1e30f

#define DIST_OFF 16384
#define A_OFF    (16384 + 1024*6400)

typedef unsigned long long u64;

// ---------------- f32x2 packed helpers ----------------
__device__ __forceinline__ u64 pk2(float lo, float hi) {
    u64 r; asm("mov.b64 %0,{%1,%2};" : "=l"(r) : "f"(lo), "f"(hi)); return r;
}
__device__ __forceinline__ u64 dup2(float v) { return pk2(v, v); }
__device__ __forceinline__ void up2(u64 v, float& a, float& b) {
    asm("mov.b64 {%0,%1},%2;" : "=f"(a), "=f"(b) : "l"(v));
}
__device__ __forceinline__ u64 fma2(u64 a, u64 b, u64 c) {
    u64 d; asm("fma.rn.f32x2 %0,%1,%2,%3;" : "=l"(d) : "l"(a), "l"(b), "l"(c)); return d;
}
__device__ __forceinline__ float f4c(const float4& v, int kk) {
    return (kk == 0) ? v.x : (kk == 1) ? v.y : (kk == 2) ? v.z : v.w;
}

// ---------------- device scratch / prepped constants ----------------
__device__ float g_x[BB * NN_ * CC];
__device__ float g_An11[64 * 64];
__device__ float g_An22[16 * 16];
__device__ unsigned int g_AtmBits[32];
__device__ float g_Wg1aT[52 * 64];   // [k][o], row 51 zero
__device__ float g_Wg2aT[51 * 64];   // [k][o]
__device__ float g_Wg1bT[64 * 64];   // [h][o2], o2>=50 zero
__device__ float g_thetaB[52 * 64];  // [c][r], r>=50 zero, rows 50,51 zero
__device__ float g_coef;

// =====================================================================
// setup work: executed by one extra block of k_mlp (256 threads)
// =====================================================================
__device__ void do_setup(float* sh,
                         const float* __restrict__ M, const float* __restrict__ Wk,
                         const float* __restrict__ smoothing,
                         const float* __restrict__ Wg1a, const float* __restrict__ Wg1b,
                         const float* __restrict__ Wg2a,
                         float* __restrict__ outA)
{
    float* sM = sh;                 // 80*26
    float* sA = sM + NN_ * DM_;     // 80*80
    float* d1 = sA + NN_ * NN_;     // 64
    float* d2 = d1 + 64;            // 16
    const int tid = threadIdx.x;
    const int lane = tid & 31, warp = tid >> 5;

    for (int e = tid; e < NN_ * DM_; e += 256) sM[e] = M[e];
    for (int e = tid; e < NN_ * NN_; e += 256) sA[e] = 0.f;
    __syncthreads();

    for (int p = warp; p < NN_; p += 8) {
        float vals[3];
        float mx = NEGV;
        int cnt = 0;
        for (int q = lane; q < p; q += 32) {
            float s = 0.f;
            #pragma unroll
            for (int k = 0; k < DM_; k++) s = fmaf(sM[p * DM_ + k], sM[q * DM_ + k], s);
            s = fmaxf(s, 0.f);
            vals[cnt++] = s;
            mx = fmaxf(mx, s);
        }
        #pragma unroll
        for (int off = 16; off; off >>= 1) mx = fmaxf(mx, __shfl_xor_sync(0xffffffffu, mx, off));
        float sum = 0.f;
        for (int c = 0; c < cnt; c++) { vals[c] = expf(vals[c] - mx); sum += vals[c]; }
        #pragma unroll
        for (int off = 16; off; off >>= 1) sum += __shfl_xor_sync(0xffffffffu, sum, off);
        float inv = (p > 0) ? 1.f / sum : 0.f;
        cnt = 0;
        for (int q = lane; q < p; q += 32) sA[p * NN_ + q] = vals[cnt++] * inv;
    }
    __syncthreads();

    for (int e = tid; e < NN_ * NN_; e += 256) outA[e] = sA[e];

    if (tid < 64) {
        int c = 0;
        for (int q = 0; q < 64; q++) c += (sA[tid * NN_ + q] > 1e-15f) ? 1 : 0;
        d1[tid] = rsqrtf(1.f + (float)c);
    } else if (tid < 80) {
        int p = tid;
        int c = 0;
        for (int q = 64; q < 80; q++) c += (sA[p * NN_ + q] > 1e-15f) ? 1 : 0;
        d2[tid - 64] = rsqrtf(1.f + (float)c);
    }
    __syncthreads();

    for (int e = tid; e < 64 * 64; e += 256) {
        int p = e >> 6, q = e & 63;
        g_An11[e] = d1[p] * sA[p * NN_ + q] * d1[q];
    }
    if (tid < 256) {
        int p = tid >> 4, q = tid & 15;
        g_An22[tid] = d2[p] * sA[(64 + p) * NN_ + 64 + q] * d2[q];
    }

    if (tid < 16) {
        int p = 64 + tid;
        float mx = NEGV;
        for (int i = 0; i < 64; i++) {
            float a = sA[p * NN_ + i];
            mx = fmaxf(mx, (a != 0.f) ? a : NEGV);
        }
        float sum = 0.f;
        for (int i = 0; i < 64; i++) {
            float a = sA[p * NN_ + i];
            sum += expf(((a != 0.f) ? a : NEGV) - mx);
        }
        float inv = 1.f / sum;
        unsigned int b0 = 0u, b1 = 0u;
        for (int i = 0; i < 64; i++) {
            float a = sA[p * NN_ + i];
            float v = expf(((a != 0.f) ? a : NEGV) - mx) * inv;
            if (v >= 0.004f) {
                if (i < 32) b0 |= (1u << i);
                else        b1 |= (1u << (i - 32));
            }
        }
        g_AtmBits[tid * 2]     = b0;
        g_AtmBits[tid * 2 + 1] = b1;
    }

    // theta (padded): rows >=50 zero, cols r>=50 zero
    for (int e = tid; e < 52 * 64; e += 256) {
        int c = e >> 6, r = e & 63;
        float s = 0.f;
        if (c < 50 && r < 50) {
            #pragma unroll 8
            for (int k = 0; k < 64; k++) s = fmaf(Wk[c * 64 + k], Wk[r * 64 + k], s);
        }
        g_thetaB[e] = s;
    }

    // transposed weights
    for (int e = tid; e < 52 * 64; e += 256) {
        int k = e >> 6, o = e & 63;
        g_Wg1aT[e] = (k < 51) ? Wg1a[o * 51 + k] : 0.f;
    }
    for (int e = tid; e < 51 * 64; e += 256) {
        int k = e >> 6, o = e & 63;
        g_Wg2aT[e] = Wg2a[o * 51 + k];
    }
    for (int e = tid; e < 64 * 64; e += 256) {
        int h = e >> 6, o = e & 63;
        g_Wg1bT[e] = (o < 50) ? Wg1b[o * 64 + h] : 0.f;
    }

    if (tid == 0) {
        float sg = 1.f / (1.f + expf(-smoothing[0]));
        g_coef = -0.5f / (sg * 0.01f);
    }
}

// =====================================================================
// Kernel 1: gather + 3-layer MLP (round-7 config, unchanged).
// =====================================================================
#define PT  68   // token buffer pitch (mult of 4)
#define PW1 52   // staged w1 pitch (mult of 4)

__global__ void __launch_bounds__(256, 3) k_mlp(
    const float* __restrict__ data,
    const float* __restrict__ emb0, const float* __restrict__ emb1, const float* __restrict__ emb2,
    const float* __restrict__ w1, const float* __restrict__ b1,
    const float* __restrict__ w2, const float* __restrict__ b2,
    const float* __restrict__ w3, const float* __restrict__ b3,
    const float* __restrict__ M, const float* __restrict__ Wk,
    const float* __restrict__ smoothing,
    const float* __restrict__ Wg1a, const float* __restrict__ Wg1b,
    const float* __restrict__ Wg2a,
    float* __restrict__ outA)
{
    extern __shared__ float sh[];

    if (blockIdx.x == 1280) {
        do_setup(sh, M, Wk, smoothing, Wg1a, Wg1b, Wg2a, outA);
        return;
    }

    float* T     = sh;               // 128 * PT (feature-major: [feat][token])
    float* w1s   = T + 128 * PT;     // 128 * PW1
    float* sLast = w1s + 128 * PW1;  // 64

    const int tid = threadIdx.x;
    const int cx = tid & 15, ry = tid >> 4;
    const int base = blockIdx.x * 64;

    if (tid < 64) sLast[tid] = data[(size_t)(base + tid) * 6 + 5];

    // stage w1 (128 x 51 -> pitch 52, col 51 zero)
    for (int e = tid; e < 128 * PW1; e += 256) {
        int o = e / PW1, k = e % PW1;
        w1s[e] = (k < 51) ? w1[o * 51 + k] : 0.f;
    }
    // gather X^T (52 x 64): T[c][t], row 51 zero
    for (int e = tid; e < 52 * 64; e += 256) {
        int c = e >> 6, t = e & 63;
        const float* dr = data + (size_t)(base + t) * 6;
        float v;
        if (c < 32)      { int i0 = (int)dr[0]; v = emb0[i0 * 32 + c]; }
        else if (c < 40) { int i1 = (int)dr[1]; v = emb1[i1 * 8 + (c - 32)]; }
        else if (c < 48) { int i2 = (int)dr[2]; v = emb2[i2 * 8 + (c - 40)]; }
        else if (c < 51) { v = dr[3 + (c - 48)]; }
        else             { v = 0.f; }
        T[c * PT + t] = v;
    }
    __syncthreads();

    // ---- GEMM1: h1[o][t] = relu(w1s @ T + b1), K=52 ----
    {
        u64 acc[8][2];
        #pragma unroll
        for (int i = 0; i < 8; i++) { acc[i][0] = 0ull; acc[i][1] = 0ull; }
        for (int k0 = 0; k0 < 52; k0 += 4) {
            float4 ap[8];
            #pragma unroll
            for (int i = 0; i < 8; i++)
                ap[i] = *reinterpret_cast<const float4*>(&w1s[(ry + 16 * i) * PW1 + k0]);
            #pragma unroll
            for (int kk = 0; kk < 4; kk++) {
                ulonglong2 bv = *reinterpret_cast<const ulonglong2*>(&T[(k0 + kk) * PT + 4 * cx]);
                #pragma unroll
                for (int i = 0; i < 8; i++) {
                    u64 ad = dup2(f4c(ap[i], kk));
                    acc[i][0] = fma2(ad, bv.x, acc[i][0]);
                    acc[i][1] = fma2(ad, bv.y, acc[i][1]);
                }
            }
        }
        __syncthreads();
        #pragma unroll
        for (int i = 0; i < 8; i++) {
            int o = ry + 16 * i;
            float bo = __ldg(&b1[o]);
            float4 v;
            up2(acc[i][0], v.x, v.y);
            up2(acc[i][1], v.z, v.w);
            v.x = fmaxf(v.x + bo, 0.f); v.y = fmaxf(v.y + bo, 0.f);
            v.z = fmaxf(v.z + bo, 0.f); v.w = fmaxf(v.w + bo, 0.f);
            *reinterpret_cast<float4*>(&T[o * PT + 4 * cx]) = v;
        }
        __syncthreads();
    }

    // ---- GEMM2: h2 = relu(w2 @ T + b2), K=128 ----
    {
        u64 acc[8][2];
        #pragma unroll
        for (int i = 0; i < 8; i++) { acc[i][0] = 0ull; acc[i][1] = 0ull; }
        #pragma unroll 2
        for (int k0 = 0; k0 < 128; k0 += 4) {
            float4 ap[8];
            #pragma unroll
            for (int i = 0; i < 8; i++)
                ap[i] = *reinterpret_cast<const float4*>(&w2[(ry + 16 * i) * 128 + k0]);
            #pragma unroll
            for (int kk = 0; kk < 4; kk++) {
                ulonglong2 bv = *reinterpret_cast<const ulonglong2*>(&T[(k0 + kk) * PT + 4 * cx]);
                #pragma unroll
                for (int i = 0; i < 8; i++) {
                    u64 ad = dup2(f4c(ap[i], kk));
                    acc[i][0] = fma2(ad, bv.x, acc[i][0]);
                    acc[i][1] = fma2(ad, bv.y, acc[i][1]);
                }
            }
        }
        __syncthreads();
        #pragma unroll
        for (int i = 0; i < 8; i++) {
            int o = ry + 16 * i;
            float bo = __ldg(&b2[o]);
            float4 v;
            up2(acc[i][0], v.x, v.y);
            up2(acc[i][1], v.z, v.w);
            v.x = fmaxf(v.x + bo, 0.f); v.y = fmaxf(v.y + bo, 0.f);
            v.z = fmaxf(v.z + bo, 0.f); v.w = fmaxf(v.w + bo, 0.f);
            *reinterpret_cast<float4*>(&T[o * PT + 4 * cx]) = v;
        }
        __syncthreads();
    }

    // ---- GEMM3: h3 = w3 @ T + b3 (o<50) -> g_x, K=128 ----
    {
        u64 acc[4][2];
        #pragma unroll
        for (int i = 0; i < 4; i++) { acc[i][0] = 0ull; acc[i][1] = 0ull; }
        #pragma unroll 2
        for (int k0 = 0; k0 < 128; k0 += 4) {
            float4 ap[4];
            #pragma unroll
            for (int i = 0; i < 4; i++) {
                int o = ry + 16 * i;
                ap[i] = (o < 50) ? *reinterpret_cast<const float4*>(&w3[o * 128 + k0])
                                 : make_float4(0.f, 0.f, 0.f, 0.f);
            }
            #pragma unroll
            for (int kk = 0; kk < 4; kk++) {
                ulonglong2 bv = *reinterpret_cast<const ulonglong2*>(&T[(k0 + kk) * PT + 4 * cx]);
                #pragma unroll
                for (int i = 0; i < 4; i++) {
                    u64 ad = dup2(f4c(ap[i], kk));
                    acc[i][0] = fma2(ad, bv.x, acc[i][0]);
                    acc[i][1] = fma2(ad, bv.y, acc[i][1]);
                }
            }
        }
        #pragma unroll
        for (int i = 0; i < 4; i++) {
            int o = ry + 16 * i;
            if (o < 50) {
                float bo = __ldg(&b3[o]);
                float v0, v1, v2, v3;
                up2(acc[i][0], v0, v1);
                up2(acc[i][1], v2, v3);
                int t = base + 4 * cx;
                g_x[(size_t)(t + 0) * CC + o] = v0 + bo;
                g_x[(size_t)(t + 1) * CC + o] = v1 + bo;
                g_x[(size_t)(t + 2) * CC + o] = v2 + bo;
                g_x[(size_t)(t + 3) * CC + o] = v3 + bo;
            }
        }
        if (tid < 64) g_x[(size_t)(base + tid) * CC + 50] = sLast[tid];
    }
}

// =====================================================================
// Kernel 2: per-graph pipeline. 16x32 warp tiles, aliased smem, 4 CTAs/SM.
// =====================================================================
#define PXM 52   // xs pitch (mult of 4)
#define PZB 68   // big buffer pitch (mult of 4)

// C(64x64) = A(64xK smem, pitch pa) @ B(Kx64 global, ld 64). K mult of 4.
// Warp tile 16x32 (warps 4x2); thread 4 rows x 4 cols. C may alias A.
__device__ __forceinline__ void gemm_AS_BG(const float* As, int pa,
                                           const float* __restrict__ Bg, int K,
                                           float* Cs, bool do_relu, int rg, int cg)
{
    u64 acc[4][2];
    #pragma unroll
    for (int i = 0; i < 4; i++) { acc[i][0] = 0ull; acc[i][1] = 0ull; }
    for (int k0 = 0; k0 < K; k0 += 4) {
        float4 ap[4];
        #pragma unroll
        for (int i = 0; i < 4; i++)
            ap[i] = *reinterpret_cast<const float4*>(As + (rg + i) * pa + k0);
        #pragma unroll
        for (int kk = 0; kk < 4; kk++) {
            ulonglong2 bv = *reinterpret_cast<const ulonglong2*>(Bg + (k0 + kk) * 64 + cg);
            #pragma unroll
            for (int i = 0; i < 4; i++) {
                u64 ad = dup2(f4c(ap[i], kk));
                acc[i][0] = fma2(ad, bv.x, acc[i][0]);
                acc[i][1] = fma2(ad, bv.y, acc[i][1]);
            }
        }
    }
    __syncthreads();
    #pragma unroll
    for (int i = 0; i < 4; i++) {
        float4 v;
        up2(acc[i][0], v.x, v.y);
        up2(acc[i][1], v.z, v.w);
        if (do_relu) {
            v.x = fmaxf(v.x, 0.f); v.y = fmaxf(v.y, 0.f);
            v.z = fmaxf(v.z, 0.f); v.w = fmaxf(v.w, 0.f);
        }
        *reinterpret_cast<float4*>(&Cs[(rg + i) * PZB + cg]) = v;
    }
    __syncthreads();
}

// C(64x64) = A(64x64 global, ld 64) @ B(64x64 smem, pitch PZB). C may alias B.
__device__ __forceinline__ void gemm_AG_BS(const float* __restrict__ Ag,
                                           const float* Bs,
                                           float* Cs, bool do_relu, int rg, int cg)
{
    u64 acc[4][2];
    #pragma unroll
    for (int i = 0; i < 4; i++) { acc[i][0] = 0ull; acc[i][1] = 0ull; }
    for (int k0 = 0; k0 < 64; k0 += 4) {
        float4 ap[4];
        #pragma unroll
        for (int i = 0; i < 4; i++)
            ap[i] = *reinterpret_cast<const float4*>(Ag + (rg + i) * 64 + k0);
        #pragma unroll
        for (int kk = 0; kk < 4; kk++) {
            ulonglong2 bv = *reinterpret_cast<const ulonglong2*>(&Bs[(k0 + kk) * PZB + cg]);
            #pragma unroll
            for (int i = 0; i < 4; i++) {
                u64 ad = dup2(f4c(ap[i], kk));
                acc[i][0] = fma2(ad, bv.x, acc[i][0]);
                acc[i][1] = fma2(ad, bv.y, acc[i][1]);
            }
        }
    }
    __syncthreads();
    #pragma unroll
    for (int i = 0; i < 4; i++) {
        float4 v;
        up2(acc[i][0], v.x, v.y);
        up2(acc[i][1], v.z, v.w);
        if (do_relu) {
            v.x = fmaxf(v.x, 0.f); v.y = fmaxf(v.y, 0.f);
            v.z = fmaxf(v.z, 0.f); v.w = fmaxf(v.w, 0.f);
        }
        *reinterpret_cast<float4*>(&Cs[(rg + i) * PZB + cg]) = v;
    }
    __syncthreads();
}

__global__ void __launch_bounds__(256, 4) k_main(
    const float* __restrict__ Wg2b,
    float* __restrict__ dout)
{
    extern __shared__ float sh[];
    float* xs  = sh;                 // 80*PXM = 4160
    float* B1  = xs + 80 * PXM;      // 64*PZB = 4352
    float* B2  = B1 + 64 * PZB;      // 64*PZB = 4352
    float* z3  = B2 + 64 * PZB;      // 16*PZB = 1088 (v / z3g buffer)
    float* yhv = z3 + 16 * PZB;      // 16
    float* z4v = yhv + 16;           // 16
    float* sqv = z4v + 16;           // 80
    float* Ls  = B1;                 // alias (dead u rows after q-form)
    float* t2b = B2;                 // alias (dead x1 rows after q-form)

    const int tid = threadIdx.x;
    const int w = tid >> 5, lane = tid & 31;
    const int rg = (w >> 1) * 16 + (lane >> 3) * 4;   // gemm base row (4 rows)
    const int cg = (w & 1) * 32 + (lane & 7) * 4;     // gemm base col (4 cols)
    const int tx = tid & 15, ty16 = tid >> 4;         // 16x16 sections
    const int b = blockIdx.x;
    const float* gx = g_x + (size_t)b * NN_ * CC;

    // -------- load per-graph features (pitch 52, col 51 zero) --------
    for (int e = tid; e < 80 * PXM; e += 256) {
        int r = e / PXM, c = e % PXM;
        xs[e] = (c < 51) ? gx[r * 51 + c] : 0.f;
    }
    __syncthreads();

    // -------- gcnn1 chain --------
    gemm_AS_BG(xs, PXM, g_Wg1aT, 52, B1, false, rg, cg);   // z1
    gemm_AG_BS(g_An11, B1, B1, true, rg, cg);              // t1 = relu(An11 @ z1)
    gemm_AS_BG(B1, PZB, g_Wg1bT, 64, B1, false, rg, cg);   // z2
    gemm_AG_BS(g_An11, B1, B2, false, rg, cg);             // x1 -> B2
    gemm_AS_BG(B2, PZB, g_thetaB, 52, B1, false, rg, cg);  // u  -> B1

    // -------- v = xf @ theta (16x64) -> z3 --------
    {
        u64 acc[2] = {0ull, 0ull};
        for (int k = 0; k < 50; k += 2) {
            float2 a = *reinterpret_cast<const float2*>(&xs[(64 + ty16) * PXM + k]);
            u64 a0 = dup2(a.x), a1 = dup2(a.y);
            acc[0] = fma2(a0, *reinterpret_cast<const u64*>(&g_thetaB[k * 64 + 2 * tx]), acc[0]);
            acc[1] = fma2(a0, *reinterpret_cast<const u64*>(&g_thetaB[k * 64 + 2 * tx + 32]), acc[1]);
            acc[0] = fma2(a1, *reinterpret_cast<const u64*>(&g_thetaB[(k + 1) * 64 + 2 * tx]), acc[0]);
            acc[1] = fma2(a1, *reinterpret_cast<const u64*>(&g_thetaB[(k + 1) * 64 + 2 * tx + 32]), acc[1]);
        }
        __syncthreads();
        #pragma unroll
        for (int j = 0; j < 2; j++) {
            float v0, v1; up2(acc[j], v0, v1);
            int c = 2 * tx + 32 * j;
            z3[ty16 * PZB + c] = v0;
            z3[ty16 * PZB + c + 1] = v1;
        }
        __syncthreads();
    }

    // -------- q[j][i] = (xp_i - xf_j).(u_i - v_j) -> masked logits Ls --------
    {
        float cf = g_coef;
        float acc[4] = {0.f, 0.f, 0.f, 0.f};
        for (int k = 0; k < 50; k += 2) {
            float2 xf2 = *reinterpret_cast<const float2*>(&xs[(64 + ty16) * PXM + k]);
            float2 v2  = *reinterpret_cast<const float2*>(&z3[ty16 * PZB + k]);
            #pragma unroll
            for (int j = 0; j < 4; j++) {
                int i = tx + 16 * j;
                float2 b2v = *reinterpret_cast<const float2*>(&B2[i * PZB + k]);
                float2 b1v = *reinterpret_cast<const float2*>(&B1[i * PZB + k]);
                acc[j] = fmaf(b2v.x - xf2.x, b1v.x - v2.x, acc[j]);
                acc[j] = fmaf(b2v.y - xf2.y, b1v.y - v2.y, acc[j]);
            }
        }
        unsigned int m0 = __ldg(&g_AtmBits[ty16 * 2]);
        unsigned int m1 = __ldg(&g_AtmBits[ty16 * 2 + 1]);
        __syncthreads();   // all reads of B1 (u) / B2 (x1) complete before alias writes
        #pragma unroll
        for (int j = 0; j < 4; j++) {
            int i = tx + 16 * j;
            bool on = (i < 32) ? ((m0 >> i) & 1u) : ((m1 >> (i - 32)) & 1u);
            Ls[ty16 * PZB + i] = on ? (cf * acc[j]) : NEGV;
        }
        __syncthreads();
    }

    // -------- softmax over j --------
    if (tid < 64) {
        int i = tid;
        float m = NEGV;
        for (int j = 0; j < 16; j++) m = fmaxf(m, Ls[j * PZB + i]);
        float s = 0.f;
        for (int j = 0; j < 16; j++) {
            float e = expf(Ls[j * PZB + i] - m);
            Ls[j * PZB + i] = e;
            s += e;
        }
        float inv = 1.f / s;
        for (int j = 0; j < 16; j++) Ls[j * PZB + i] *= inv;
    }
    __syncthreads();

    // -------- yh, splice --------
    if (tid < 16) {
        float s = 0.f;
        for (int i = 0; i < 64; i++) s = fmaf(Ls[tid * PZB + i], xs[i * PXM + 50], s);
        yhv[tid] = s;
    }
    __syncthreads();
    if (tid < 16) xs[(64 + tid) * PXM + 50] = yhv[tid];
    __syncthreads();

    // -------- gcnn2: z3g = x2 @ Wg2a^T (16x64), K=51 -> z3 --------
    {
        u64 acc[2] = {0ull, 0ull};
        for (int k = 0; k < 50; k += 2) {
            float2 a = *reinterpret_cast<const float2*>(&xs[(64 + ty16) * PXM + k]);
            u64 a0 = dup2(a.x), a1 = dup2(a.y);
            acc[0] = fma2(a0, *reinterpret_cast<const u64*>(&g_Wg2aT[k * 64 + 2 * tx]), acc[0]);
            acc[1] = fma2(a0, *reinterpret_cast<const u64*>(&g_Wg2aT[k * 64 + 2 * tx + 32]), acc[1]);
            acc[0] = fma2(a1, *reinterpret_cast<const u64*>(&g_Wg2aT[(k + 1) * 64 + 2 * tx]), acc[0]);
            acc[1] = fma2(a1, *reinterpret_cast<const u64*>(&g_Wg2aT[(k + 1) * 64 + 2 * tx + 32]), acc[1]);
        }
        { // k = 50
            u64 a0 = dup2(xs[(64 + ty16) * PXM + 50]);
            acc[0] = fma2(a0, *reinterpret_cast<const u64*>(&g_Wg2aT[50 * 64 + 2 * tx]), acc[0]);
            acc[1] = fma2(a0, *reinterpret_cast<const u64*>(&g_Wg2aT[50 * 64 + 2 * tx + 32]), acc[1]);
        }
        __syncthreads();
        #pragma unroll
        for (int j = 0; j < 2; j++) {
            float v0, v1; up2(acc[j], v0, v1);
            int c = 2 * tx + 32 * j;
            z3[ty16 * PZB + c] = v0;
            z3[ty16 * PZB + c + 1] = v1;
        }
        __syncthreads();
    }
    // -------- t2 = relu(An22 @ z3g) -> t2b (alias B2) --------
    {
        u64 acc[2] = {0ull, 0ull};
        for (int q = 0; q < 16; q++) {
            u64 ad = dup2(__ldg(&g_An22[ty16 * 16 + q]));
            acc[0] = fma2(ad, *reinterpret_cast<const u64*>(&z3[q * PZB + 2 * tx]), acc[0]);
            acc[1] = fma2(ad, *reinterpret_cast<const u64*>(&z3[q * PZB + 2 * tx + 32]), acc[1]);
        }
        __syncthreads();
        #pragma unroll
        for (int j = 0; j < 2; j++) {
            float v0, v1; up2(acc[j], v0, v1);
            int c = 2 * tx + 32 * j;
            t2b[ty16 * PZB + c]     = fmaxf(v0, 0.f);
            t2b[ty16 * PZB + c + 1] = fmaxf(v1, 0.f);
        }
        __syncthreads();
    }
    if (tid < 16) {
        float s = 0.f;
        for (int c = 0; c < 64; c++) s = fmaf(t2b[tid * PZB + c], __ldg(&Wg2b[c]), s);
        z4v[tid] = s;
    }
    __syncthreads();
    if (tid < 16) {
        float s = 0.f;
        for (int q = 0; q < 16; q++) s = fmaf(__ldg(&g_An22[tid * 16 + q]), z4v[q], s);
        dout[b * 16 + tid] = s;
    }

    // -------- pairwise dist on xc (80x52, col 51 zero) --------
    if (tid < 80) {
        float s = 0.f;
        for (int c = 0; c < 51; c++) {
            float v = xs[tid * PXM + c];
            s = fmaf(v, v, s);
        }
        sqv[tid] = s;
    }
    __syncthreads();
    {
        float acc[5][5];
        #pragma unroll
        for (int i = 0; i < 5; i++)
            #pragma unroll
            for (int j = 0; j < 5; j++) acc[i][j] = 0.f;
        for (int k0 = 0; k0 < 52; k0 += 2) {
            float2 a2[5], b2[5];
            #pragma unroll
            for (int i = 0; i < 5; i++)
                a2[i] = *reinterpret_cast<const float2*>(&xs[(ty16 * 5 + i) * PXM + k0]);
            #pragma unroll
            for (int j = 0; j < 5; j++)
                b2[j] = *reinterpret_cast<const float2*>(&xs[(tx * 5 + j) * PXM + k0]);
            #pragma unroll
            for (int i = 0; i < 5; i++)
                #pragma unroll
                for (int j = 0; j < 5; j++) {
                    acc[i][j] = fmaf(a2[i].x, b2[j].x, acc[i][j]);
                    acc[i][j] = fmaf(a2[i].y, b2[j].y, acc[i][j]);
                }
        }
        float* dd = dout + DIST_OFF + (size_t)b * 6400;
        #pragma unroll
        for (int i = 0; i < 5; i++)
            #pragma unroll
            for (int j = 0; j < 5; j++) {
                int n = ty16 * 5 + i, m = tx * 5 + j;
                float d2 = sqv[n] + sqv[m] - 2.f * acc[i][j];
                dd[n * 80 + m] = (d2 > 0.f) ? sqrtf(d2) : 0.f;
            }
    }
}

// =====================================================================
// launcher
// =====================================================================
extern "C" void kernel_launch(void* const* d_in, const int* in_sizes, int n_in,
                              void* d_out, int out_size)
{
    const float* data  = (const float*)d_in[0];
    const float* emb0  = (const float*)d_in[1];
    const float* emb1  = (const float*)d_in[2];
    const float* emb2  = (const float*)d_in[3];
    const float* w1    = (const float*)d_in[4];
    const float* b1    = (const float*)d_in[5];
    const float* w2    = (const float*)d_in[6];
    const float* b2    = (const float*)d_in[7];
    const float* w3    = (const float*)d_in[8];
    const float* b3    = (const float*)d_in[9];
    const float* M     = (const float*)d_in[10];
    const float* Wg1a  = (const float*)d_in[11];
    const float* Wg1b  = (const float*)d_in[12];
    const float* Wk    = (const float*)d_in[13];
    const float* smoothing = (const float*)d_in[14];
    const float* Wg2a  = (const float*)d_in[15];
    const float* Wg2b  = (const float*)d_in[16];
    float* out = (float*)d_out;

    const int SMEM_MLP  = (128 * PT + 128 * PW1 + 64) * 4;
    const int SMEM_MAIN = (80 * PXM + 2 * 64 * PZB + 16 * PZB + 16 + 16 + 80) * 4;

    cudaFuncSetAttribute(k_mlp, cudaFuncAttributeMaxDynamicSharedMemorySize, SMEM_MLP);
    cudaFuncSetAttribute(k_main, cudaFuncAttributeMaxDynamicSharedMemorySize, SMEM_MAIN);

    k_mlp<<<1281, 256, SMEM_MLP>>>(data, emb0, emb1, emb2, w1, b1, w2, b2, w3, b3,
                                   M, Wk, smoothing, Wg1a, Wg1b, Wg2a, out + A_OFF);
    k_main<<<1024, 256, SMEM_MAIN>>>(Wg2b, out);
}